// round 14
// baseline (speedup 1.0000x reference)
#include <cuda_runtime.h>
#include <cstdint>
#include <cstddef>

// Jordan GRU, B=128, T=2048, I=128, H=256, O=64.
// 16 groups x 8 slices; CTA = 8 batch rows x 32 hidden units, 512 threads.
// Thread = (K-quarter q, unit, batch-pair) -> 2 rows per thread.
// Single exchange per step (hnew + fc partials under one release flag).
// R12 + direct h publish from q1 and a 256-thread tail barrier: half the
// warps skip the publish tail entirely.

#define TSTEPS 2048
#define INSZ 128
#define HID 256
#define OUTSZ 64
#define GIN 192
#define NBLK 128
#define NTHR 512
#define ROWS 8
#define UNITS 32
#define NSLICE 8

#define HS 260
#define XS 132
#define XBUF 1056     // one x buffer (8 * 132)
#define YS 68
#define WHS 260
#define WIS 196
#define FST 36
#define HSTG 36

// float offsets in dynamic smem
#define OFF_H    0                            // 8*260  = 2080
#define OFF_X    2080                         // 2*1056 = 2112
#define OFF_Y    4192                         // 8*68   = 544
#define OFF_P    4736                         // 3*256 float4 = 3072
#define OFF_HST  7808                         // 8*36   = 288
#define OFF_WHH  8096                         // 96*260 = 24960
#define OFF_WIH  33056                        // 96*196 = 18816
#define OFF_FC2  51872                        // 64*36  = 2304
#define OFF_BIH  54176                        // 96
#define OFF_BHH  54272                        // 96
#define OFF_FCB  54368                        // 64
#define SMEM_FLOATS 54448                     // 217,792 B

typedef unsigned long long ull;

__device__ float g_h[2][128 * HID];           // [buf][b][k]
__device__ float g_yp[2][128 * 512];          // [buf][b][slice][o]
__device__ unsigned g_hflag[NBLK];

__device__ __forceinline__ ull ffma2(ull a, ull b, ull c) {
    ull d; asm("fma.rn.f32x2 %0, %1, %2, %3;" : "=l"(d) : "l"(a), "l"(b), "l"(c));
    return d;
}
__device__ __forceinline__ float sumf2(ull v) {
    float a, b; asm("mov.b64 {%0, %1}, %2;" : "=f"(a), "=f"(b) : "l"(v));
    return a + b;
}
__device__ __forceinline__ unsigned ld_acq(const unsigned* p) {
    unsigned v; asm volatile("ld.acquire.gpu.global.u32 %0, [%1];" : "=r"(v) : "l"(p));
    return v;
}
__device__ __forceinline__ void st_rel(unsigned* p, unsigned v) {
    asm volatile("st.release.gpu.global.u32 [%0], %1;" :: "l"(p), "r"(v));
}
__device__ __forceinline__ void barn(int id, int cnt) {
    asm volatile("bar.sync %0, %1;" :: "r"(id), "r"(cnt) : "memory");
}

__global__ void jordan_init_kernel() {
    int i = blockIdx.x * blockDim.x + threadIdx.x;
    if (i < NBLK) g_hflag[i] = 0u;
}

__global__ void __launch_bounds__(NTHR, 1) jordan_kernel(
    const float* __restrict__ x,      // [B, T, I]
    const float* __restrict__ w_ih,   // [3H, GIN]
    const float* __restrict__ w_hh,   // [3H, H]
    const float* __restrict__ b_ih,   // [3H]
    const float* __restrict__ b_hh,   // [3H]
    const float* __restrict__ fc_w,   // [O, H]
    const float* __restrict__ fc_b,   // [O]
    float* __restrict__ out)          // [B, O]
{
    extern __shared__ float sm[];
    float*  h_s    = sm + OFF_H;
    float*  x_s    = sm + OFF_X;      // [2][8][XS]
    float*  y_s    = sm + OFF_Y;
    float4* p_s    = reinterpret_cast<float4*>(sm + OFF_P);
    float*  hstg_s = sm + OFF_HST;
    float*  whh_s  = sm + OFF_WHH;
    float*  wih_s  = sm + OFF_WIH;
    float*  fc2_s  = sm + OFF_FC2;
    float*  bih_s  = sm + OFF_BIH;
    float*  bhh_s  = sm + OFF_BHH;
    float*  fcb_s  = sm + OFF_FCB;

    const int tid  = threadIdx.x;
    const int q    = tid >> 7;          // K-quarter 0..3
    const int wg   = tid & 127;
    const int unit = wg >> 2;           // 0..31
    const int b    = wg & 3;            // rows b and b+4

    const int blk   = blockIdx.x;
    const int group = blk >> 3;
    const int slice = blk & 7;
    const int b0    = group * ROWS;
    const int fbase = group * NSLICE;

    // y-partial workers: warps 2,3 (rows 0-3) and 10,11 (rows 4-7)
    int yo = -1, rb = 0;
    if (tid >= 64 && tid < 128)        { yo = tid - 64;  rb = 0; }
    else if (tid >= 320 && tid < 384)  { yo = tid - 320; rb = 4; }

    // tail participants: q1 warps (4-7) + ypart warps (2,3,10,11) = 256 thr
    const bool in_tail = (tid >= 64 && tid < 256) || (tid >= 320 && tid < 384);

    // ---- load weights / biases, zero state ----
    for (int i = tid; i < 96 * HID; i += NTHR) {
        int row = i >> 8, k = i & 255;
        whh_s[row * WHS + k] =
            w_hh[((row >> 5) * HID + slice * UNITS + (row & 31)) * HID + k];
    }
    for (int i = tid; i < 96 * GIN; i += NTHR) {
        int row = i / GIN, k = i - row * GIN;
        wih_s[row * WIS + k] =
            w_ih[((row >> 5) * HID + slice * UNITS + (row & 31)) * GIN + k];
    }
    for (int i = tid; i < OUTSZ * 32; i += NTHR) {
        int o = i >> 5, k = i & 31;
        fc2_s[o * FST + k] = fc_w[o * HID + slice * 32 + k];
    }
    if (tid < 96) {
        int grow = (tid >> 5) * HID + slice * UNITS + (tid & 31);
        bih_s[tid] = b_ih[grow];
        bhh_s[tid] = b_hh[grow];
    }
    if (tid < 64) fcb_s[tid] = fc_b[tid];
    for (int i = tid; i < ROWS * HS; i += NTHR) h_s[i] = 0.0f;
    for (int i = tid; i < ROWS * YS; i += NTHR) y_s[i] = 0.0f;

    // stage x_0 into buffer 0, prefetch x_1
    float4 xreg;
    if (tid < 256) {
        int row = tid >> 5, c = tid & 31;
        float4 v0 = reinterpret_cast<const float4*>(x)
                        [((size_t)(b0 + row) * TSTEPS) * 32 + c];
        *reinterpret_cast<float4*>(x_s + row * XS + c * 4) = v0;
        xreg = reinterpret_cast<const float4*>(x)
                   [((size_t)(b0 + row) * TSTEPS + 1) * 32 + c];
    }
    __syncthreads();

    const float* whR = whh_s + (0 * UNITS + unit) * WHS + q * 64;
    const float* whZ = whh_s + (1 * UNITS + unit) * WHS + q * 64;
    const float* whN = whh_s + (2 * UNITS + unit) * WHS + q * 64;
    const float* wxR = wih_s + (0 * UNITS + unit) * WIS + q * 32;
    const float* wxZ = wih_s + (1 * UNITS + unit) * WIS + q * 32;
    const float* wxN = wih_s + (2 * UNITS + unit) * WIS + q * 32;
    const float* wyR = wih_s + (0 * UNITS + unit) * WIS + INSZ + q * 16;
    const float* wyZ = wih_s + (1 * UNITS + unit) * WIS + INSZ + q * 16;
    const float* wyN = wih_s + (2 * UNITS + unit) * WIS + INSZ + q * 16;

    const int srow = tid >> 6;           // staging row 0..7
    const int scol = tid & 63;           // staging col / output index

    for (int t = 0; t < TSTEPS; t++) {
        const int cur = t & 1, nxt = cur ^ 1;

        // ---- A: store x_{t+1} into xbuf[nxt]; prefetch x_{t+2} ----
        if (tid < 256 && t + 1 < TSTEPS) {
            int row = tid >> 5, c = tid & 31;
            *reinterpret_cast<float4*>(x_s + nxt * XBUF + row * XS + c * 4) = xreg;
            if (t + 2 < TSTEPS)
                xreg = reinterpret_cast<const float4*>(x)
                           [((size_t)(b0 + row) * TSTEPS + t + 2) * 32 + c];
        }

        // ---- B: gi_x hoisted (independent of recurrence) ----
        float gxR0, gxZ0, gxNi0, gxR1, gxZ1, gxNi1;
        {
            const float* xb = x_s + cur * XBUF;
            const ulonglong2* x0 = reinterpret_cast<const ulonglong2*>(xb + b * XS + q * 32);
            const ulonglong2* x1 = reinterpret_cast<const ulonglong2*>(xb + (b + 4) * XS + q * 32);
            const ulonglong2* r0 = reinterpret_cast<const ulonglong2*>(wxR);
            const ulonglong2* r1 = reinterpret_cast<const ulonglong2*>(wxZ);
            const ulonglong2* r2 = reinterpret_cast<const ulonglong2*>(wxN);
            ull xR0 = 0, xZ0 = 0, xN0 = 0, xR1 = 0, xZ1 = 0, xN1 = 0;
            #pragma unroll 8
            for (int c = 0; c < 8; c++) {
                ulonglong2 v0 = r0[c], xv0 = x0[c], xv1 = x1[c];
                xR0 = ffma2(xv0.x, v0.x, xR0); xR0 = ffma2(xv0.y, v0.y, xR0);
                xR1 = ffma2(xv1.x, v0.x, xR1); xR1 = ffma2(xv1.y, v0.y, xR1);
                ulonglong2 v1 = r1[c];
                xZ0 = ffma2(xv0.x, v1.x, xZ0); xZ0 = ffma2(xv0.y, v1.y, xZ0);
                xZ1 = ffma2(xv1.x, v1.x, xZ1); xZ1 = ffma2(xv1.y, v1.y, xZ1);
                ulonglong2 v2 = r2[c];
                xN0 = ffma2(xv0.x, v2.x, xN0); xN0 = ffma2(xv0.y, v2.y, xN0);
                xN1 = ffma2(xv1.x, v2.x, xN1); xN1 = ffma2(xv1.y, v2.y, xN1);
            }
            gxR0 = sumf2(xR0); gxZ0 = sumf2(xZ0); gxNi0 = sumf2(xN0);
            gxR1 = sumf2(xR1); gxZ1 = sumf2(xZ1); gxNi1 = sumf2(xN1);
        }

        // ---- C: 8 pollers, full barrier, stage ----
        if (t > 0) {
            if (tid < NSLICE) { while ((int)ld_acq(&g_hflag[fbase + tid]) < t) { } }
        }
        __syncthreads();                                   // S1
        if (t > 0) {
            float4 v = reinterpret_cast<const float4*>(g_h[cur])[(b0 + srow) * 64 + scol];
            *reinterpret_cast<float4*>(h_s + srow * HS + scol * 4) = v;
            const float* gp = g_yp[cur] + (b0 + srow) * 512 + scol;
            float s = fcb_s[scol];
            #pragma unroll
            for (int si = 0; si < 8; si++) s += gp[si * 64];
            y_s[srow * YS + scol] = tanhf(s);
        }
        __syncthreads();                                   // S2

        ull aR0 = 0, aR1 = 0, aZ0 = 0, aZ1 = 0;
        ull aNi0 = 0, aNi1 = 0, aNh0 = 0, aNh1 = 0;

        // ---- D: gh (quarter of K=256, 2 rows) ----
        {
            const ulonglong2* h0 = reinterpret_cast<const ulonglong2*>(h_s + b * HS + q * 64);
            const ulonglong2* h1 = reinterpret_cast<const ulonglong2*>(h_s + (b + 4) * HS + q * 64);
            const ulonglong2* r0 = reinterpret_cast<const ulonglong2*>(whR);
            const ulonglong2* r1 = reinterpret_cast<const ulonglong2*>(whZ);
            const ulonglong2* r2 = reinterpret_cast<const ulonglong2*>(whN);
            #pragma unroll 8
            for (int c = 0; c < 16; c++) {
                ulonglong2 v0 = r0[c], hv0 = h0[c], hv1 = h1[c];
                aR0 = ffma2(hv0.x, v0.x, aR0); aR0 = ffma2(hv0.y, v0.y, aR0);
                aR1 = ffma2(hv1.x, v0.x, aR1); aR1 = ffma2(hv1.y, v0.y, aR1);
                ulonglong2 v1 = r1[c];
                aZ0 = ffma2(hv0.x, v1.x, aZ0); aZ0 = ffma2(hv0.y, v1.y, aZ0);
                aZ1 = ffma2(hv1.x, v1.x, aZ1); aZ1 = ffma2(hv1.y, v1.y, aZ1);
                ulonglong2 v2 = r2[c];
                aNh0 = ffma2(hv0.x, v2.x, aNh0); aNh0 = ffma2(hv0.y, v2.y, aNh0);
                aNh1 = ffma2(hv1.x, v2.x, aNh1); aNh1 = ffma2(hv1.y, v2.y, aNh1);
            }
        }
        // ---- gi_y (quarter of O=64, 2 rows) ----
        {
            const ulonglong2* y0 = reinterpret_cast<const ulonglong2*>(y_s + b * YS + q * 16);
            const ulonglong2* y1 = reinterpret_cast<const ulonglong2*>(y_s + (b + 4) * YS + q * 16);
            const ulonglong2* r0 = reinterpret_cast<const ulonglong2*>(wyR);
            const ulonglong2* r1 = reinterpret_cast<const ulonglong2*>(wyZ);
            const ulonglong2* r2 = reinterpret_cast<const ulonglong2*>(wyN);
            #pragma unroll
            for (int c = 0; c < 4; c++) {
                ulonglong2 v0 = r0[c], yv0 = y0[c], yv1 = y1[c];
                aR0 = ffma2(yv0.x, v0.x, aR0); aR0 = ffma2(yv0.y, v0.y, aR0);
                aR1 = ffma2(yv1.x, v0.x, aR1); aR1 = ffma2(yv1.y, v0.y, aR1);
                ulonglong2 v1 = r1[c];
                aZ0 = ffma2(yv0.x, v1.x, aZ0); aZ0 = ffma2(yv0.y, v1.y, aZ0);
                aZ1 = ffma2(yv1.x, v1.x, aZ1); aZ1 = ffma2(yv1.y, v1.y, aZ1);
                ulonglong2 v2 = r2[c];
                aNi0 = ffma2(yv0.x, v2.x, aNi0); aNi0 = ffma2(yv0.y, v2.y, aNi0);
                aNi1 = ffma2(yv1.x, v2.x, aNi1); aNi1 = ffma2(yv1.y, v2.y, aNi1);
            }
        }

        // ---- E: partial store (q0, q2, q3); q1 combines ----
        if (q != 1) {
            int slot = (q == 0) ? 0 : (q - 1);
            p_s[slot * 256 + b * 32 + unit] =
                make_float4(sumf2(aR0) + gxR0, sumf2(aZ0) + gxZ0,
                            sumf2(aNi0) + gxNi0, sumf2(aNh0));
            p_s[slot * 256 + (b + 4) * 32 + unit] =
                make_float4(sumf2(aR1) + gxR1, sumf2(aZ1) + gxZ1,
                            sumf2(aNi1) + gxNi1, sumf2(aNh1));
        }
        __syncthreads();                                   // S3

        if (q == 1) {
            float4 s0 = make_float4(sumf2(aR0) + gxR0, sumf2(aZ0) + gxZ0,
                                    sumf2(aNi0) + gxNi0, sumf2(aNh0));
            float4 s1 = make_float4(sumf2(aR1) + gxR1, sumf2(aZ1) + gxZ1,
                                    sumf2(aNi1) + gxNi1, sumf2(aNh1));
            #pragma unroll
            for (int j = 0; j < 3; j++) {
                float4 pa = p_s[j * 256 + b * 32 + unit];
                float4 pb = p_s[j * 256 + (b + 4) * 32 + unit];
                s0.x += pa.x; s0.y += pa.y; s0.z += pa.z; s0.w += pa.w;
                s1.x += pb.x; s1.y += pb.y; s1.z += pb.z; s1.w += pb.w;
            }
            float biR = bih_s[unit] + bhh_s[unit];
            float biZ = bih_s[32 + unit] + bhh_s[32 + unit];
            float biN = bih_s[64 + unit];
            float bhN = bhh_s[64 + unit];

            float r0v = 1.0f / (1.0f + __expf(-(s0.x + biR)));
            float z0v = 1.0f / (1.0f + __expf(-(s0.y + biZ)));
            float n0v = tanhf(s0.z + biN + r0v * (s0.w + bhN));
            float hp0 = h_s[b * HS + slice * UNITS + unit];
            float h0new = (1.0f - z0v) * n0v + z0v * hp0;

            float r1v = 1.0f / (1.0f + __expf(-(s1.x + biR)));
            float z1v = 1.0f / (1.0f + __expf(-(s1.y + biZ)));
            float n1v = tanhf(s1.z + biN + r1v * (s1.w + bhN));
            float hp1 = h_s[(b + 4) * HS + slice * UNITS + unit];
            float h1new = (1.0f - z1v) * n1v + z1v * hp1;

            hstg_s[b * HSTG + unit] = h0new;
            hstg_s[(b + 4) * HSTG + unit] = h1new;
            // direct h publish (scattered STG.32, HW-coalesced per warp)
            g_h[nxt][(b0 + b) * HID + slice * UNITS + unit] = h0new;
            g_h[nxt][(b0 + b + 4) * HID + slice * UNITS + unit] = h1new;
        }

        // ---- G: tail (q1 + ypart warps only); others skip to next step ----
        if (in_tail) {
            barn(4, 256);                  // hstg + h STGs visible to ypart
            if (yo >= 0) {
                const ulonglong2* fp = reinterpret_cast<const ulonglong2*>(fc2_s + yo * FST);
                ulonglong2 fr[8];
                #pragma unroll
                for (int i = 0; i < 8; i++) fr[i] = fp[i];
                #pragma unroll
                for (int r = 0; r < 4; r++) {
                    const ulonglong2* hp =
                        reinterpret_cast<const ulonglong2*>(hstg_s + (rb + r) * HSTG);
                    ull a0 = 0, a1 = 0;
                    #pragma unroll
                    for (int i = 0; i < 8; i++) {
                        ulonglong2 hv = hp[i];
                        a0 = ffma2(hv.x, fr[i].x, a0);
                        a1 = ffma2(hv.y, fr[i].y, a1);
                    }
                    g_yp[nxt][(b0 + rb + r) * 512 + slice * 64 + yo] = sumf2(a0) + sumf2(a1);
                }
                barn(5, 128);              // ypart warps 2,3,10,11
                if (tid == 64) st_rel(&g_hflag[blk], (unsigned)(t + 1));
            }
        }
        // warps 0,1,8,9,12-15 fall through to next step's A/B immediately
    }

    // ---- final: out = tanh(sum of fc partials of h_T + fcb) ----
    if (tid < NSLICE) { while ((int)ld_acq(&g_hflag[fbase + tid]) < TSTEPS) { } }
    __syncthreads();
    {
        const float* gp = g_yp[0] + (b0 + srow) * 512 + scol;  // T even -> buf 0
        float s = fcb_s[scol];
        #pragma unroll
        for (int si = 0; si < 8; si++) s += gp[si * 64];
        if ((scol >> 3) == slice)
            out[(b0 + srow) * OUTSZ + scol] = tanhf(s);
    }
}

extern "C" void kernel_launch(void* const* d_in, const int* in_sizes, int n_in,
                              void* d_out, int out_size) {
    (void)in_sizes; (void)n_in; (void)out_size;
    const float* x    = (const float*)d_in[0];
    const float* w_ih = (const float*)d_in[1];
    const float* w_hh = (const float*)d_in[2];
    const float* b_ih = (const float*)d_in[3];
    const float* b_hh = (const float*)d_in[4];
    const float* fc_w = (const float*)d_in[5];
    const float* fc_b = (const float*)d_in[6];
    float* out = (float*)d_out;

    const int smem_bytes = SMEM_FLOATS * (int)sizeof(float); // 217,792 B
    cudaFuncSetAttribute(jordan_kernel,
                         cudaFuncAttributeMaxDynamicSharedMemorySize,
                         smem_bytes);

    jordan_init_kernel<<<1, NBLK>>>();
    jordan_kernel<<<NBLK, NTHR, smem_bytes>>>(x, w_ih, w_hh, b_ih, b_hh,
                                              fc_w, fc_b, out);
}

// round 15
// speedup vs baseline: 1.2287x; 1.2287x over previous
#include <cuda_runtime.h>
#include <cstdint>
#include <cstddef>

// Jordan GRU, B=128, T=2048, I=128, H=256, O=64.
// 16 groups x 8 slices; CTA = 8 batch rows x 32 hidden units, 512 threads.
// Thread = (K-quarter q, unit, batch-pair) -> 2 rows per thread.
// Single exchange per step (hnew + fc partials under one release flag).
// R12 + narrowed S4 (320 threads) so 6 warps skip the entire publish tail,
// + own-flag poll skip.

#define TSTEPS 2048
#define INSZ 128
#define HID 256
#define OUTSZ 64
#define GIN 192
#define NBLK 128
#define NTHR 512
#define ROWS 8
#define UNITS 32
#define NSLICE 8

#define HS 260
#define XS 132
#define XBUF 1056     // one x buffer (8 * 132)
#define YS 68
#define WHS 260
#define WIS 196
#define FST 36
#define HSTG 36

// float offsets in dynamic smem
#define OFF_H    0                            // 8*260  = 2080
#define OFF_X    2080                         // 2*1056 = 2112
#define OFF_Y    4192                         // 8*68   = 544
#define OFF_P    4736                         // 3*256 float4 = 3072
#define OFF_HST  7808                         // 8*36   = 288
#define OFF_WHH  8096                         // 96*260 = 24960
#define OFF_WIH  33056                        // 96*196 = 18816
#define OFF_FC2  51872                        // 64*36  = 2304
#define OFF_BIH  54176                        // 96
#define OFF_BHH  54272                        // 96
#define OFF_FCB  54368                        // 64
#define SMEM_FLOATS 54448                     // 217,792 B

typedef unsigned long long ull;

__device__ float g_h[2][128 * HID];           // [buf][b][k]
__device__ float g_yp[2][128 * 512];          // [buf][b][slice][o]
__device__ unsigned g_hflag[NBLK];

__device__ __forceinline__ ull ffma2(ull a, ull b, ull c) {
    ull d; asm("fma.rn.f32x2 %0, %1, %2, %3;" : "=l"(d) : "l"(a), "l"(b), "l"(c));
    return d;
}
__device__ __forceinline__ float sumf2(ull v) {
    float a, b; asm("mov.b64 {%0, %1}, %2;" : "=f"(a), "=f"(b) : "l"(v));
    return a + b;
}
__device__ __forceinline__ unsigned ld_acq(const unsigned* p) {
    unsigned v; asm volatile("ld.acquire.gpu.global.u32 %0, [%1];" : "=r"(v) : "l"(p));
    return v;
}
__device__ __forceinline__ void st_rel(unsigned* p, unsigned v) {
    asm volatile("st.release.gpu.global.u32 [%0], %1;" :: "l"(p), "r"(v));
}
__device__ __forceinline__ void barn(int id, int cnt) {
    asm volatile("bar.sync %0, %1;" :: "r"(id), "r"(cnt) : "memory");
}

__global__ void jordan_init_kernel() {
    int i = blockIdx.x * blockDim.x + threadIdx.x;
    if (i < NBLK) g_hflag[i] = 0u;
}

__global__ void __launch_bounds__(NTHR, 1) jordan_kernel(
    const float* __restrict__ x,      // [B, T, I]
    const float* __restrict__ w_ih,   // [3H, GIN]
    const float* __restrict__ w_hh,   // [3H, H]
    const float* __restrict__ b_ih,   // [3H]
    const float* __restrict__ b_hh,   // [3H]
    const float* __restrict__ fc_w,   // [O, H]
    const float* __restrict__ fc_b,   // [O]
    float* __restrict__ out)          // [B, O]
{
    extern __shared__ float sm[];
    float*  h_s    = sm + OFF_H;
    float*  x_s    = sm + OFF_X;      // [2][8][XS]
    float*  y_s    = sm + OFF_Y;
    float4* p_s    = reinterpret_cast<float4*>(sm + OFF_P);
    float*  hstg_s = sm + OFF_HST;
    float*  whh_s  = sm + OFF_WHH;
    float*  wih_s  = sm + OFF_WIH;
    float*  fc2_s  = sm + OFF_FC2;
    float*  bih_s  = sm + OFF_BIH;
    float*  bhh_s  = sm + OFF_BHH;
    float*  fcb_s  = sm + OFF_FCB;

    const int tid  = threadIdx.x;
    const int q    = tid >> 7;          // K-quarter 0..3
    const int wg   = tid & 127;
    const int unit = wg >> 2;           // 0..31
    const int b    = wg & 3;            // rows b and b+4

    const int blk   = blockIdx.x;
    const int group = blk >> 3;
    const int slice = blk & 7;
    const int b0    = group * ROWS;
    const int fbase = group * NSLICE;

    // y-partial workers: warps 2,3 (rows 0-3) and 10,11 (rows 4-7)
    int yo = -1, rb = 0;
    if (tid >= 64 && tid < 128)        { yo = tid - 64;  rb = 0; }
    else if (tid >= 320 && tid < 384)  { yo = tid - 320; rb = 4; }

    // publisher set: warps 0-3 (h writers + ypart rows 0-3) and 10,11
    const bool is_pub = (tid < 128) || (tid >= 320 && tid < 384);
    // S4 participants: q1 warps (4-7, hstg writers) + all hstg readers
    // (warps 0-3, 10, 11) = 10 warps = 320 threads
    const bool in_s4  = (tid < 256) || (tid >= 320 && tid < 384);

    // ---- load weights / biases, zero state ----
    for (int i = tid; i < 96 * HID; i += NTHR) {
        int row = i >> 8, k = i & 255;
        whh_s[row * WHS + k] =
            w_hh[((row >> 5) * HID + slice * UNITS + (row & 31)) * HID + k];
    }
    for (int i = tid; i < 96 * GIN; i += NTHR) {
        int row = i / GIN, k = i - row * GIN;
        wih_s[row * WIS + k] =
            w_ih[((row >> 5) * HID + slice * UNITS + (row & 31)) * GIN + k];
    }
    for (int i = tid; i < OUTSZ * 32; i += NTHR) {
        int o = i >> 5, k = i & 31;
        fc2_s[o * FST + k] = fc_w[o * HID + slice * 32 + k];
    }
    if (tid < 96) {
        int grow = (tid >> 5) * HID + slice * UNITS + (tid & 31);
        bih_s[tid] = b_ih[grow];
        bhh_s[tid] = b_hh[grow];
    }
    if (tid < 64) fcb_s[tid] = fc_b[tid];
    for (int i = tid; i < ROWS * HS; i += NTHR) h_s[i] = 0.0f;
    for (int i = tid; i < ROWS * YS; i += NTHR) y_s[i] = 0.0f;

    // stage x_0 into buffer 0, prefetch x_1
    float4 xreg;
    if (tid < 256) {
        int row = tid >> 5, c = tid & 31;
        float4 v0 = reinterpret_cast<const float4*>(x)
                        [((size_t)(b0 + row) * TSTEPS) * 32 + c];
        *reinterpret_cast<float4*>(x_s + row * XS + c * 4) = v0;
        xreg = reinterpret_cast<const float4*>(x)
                   [((size_t)(b0 + row) * TSTEPS + 1) * 32 + c];
    }
    __syncthreads();

    const float* whR = whh_s + (0 * UNITS + unit) * WHS + q * 64;
    const float* whZ = whh_s + (1 * UNITS + unit) * WHS + q * 64;
    const float* whN = whh_s + (2 * UNITS + unit) * WHS + q * 64;
    const float* wxR = wih_s + (0 * UNITS + unit) * WIS + q * 32;
    const float* wxZ = wih_s + (1 * UNITS + unit) * WIS + q * 32;
    const float* wxN = wih_s + (2 * UNITS + unit) * WIS + q * 32;
    const float* wyR = wih_s + (0 * UNITS + unit) * WIS + INSZ + q * 16;
    const float* wyZ = wih_s + (1 * UNITS + unit) * WIS + INSZ + q * 16;
    const float* wyN = wih_s + (2 * UNITS + unit) * WIS + INSZ + q * 16;

    const int srow = tid >> 6;           // staging row 0..7
    const int scol = tid & 63;           // staging col / output index

    for (int t = 0; t < TSTEPS; t++) {
        const int cur = t & 1, nxt = cur ^ 1;

        // ---- A: store x_{t+1} into xbuf[nxt]; prefetch x_{t+2} ----
        if (tid < 256 && t + 1 < TSTEPS) {
            int row = tid >> 5, c = tid & 31;
            *reinterpret_cast<float4*>(x_s + nxt * XBUF + row * XS + c * 4) = xreg;
            if (t + 2 < TSTEPS)
                xreg = reinterpret_cast<const float4*>(x)
                           [((size_t)(b0 + row) * TSTEPS + t + 2) * 32 + c];
        }

        // ---- B: gi_x hoisted (independent of recurrence) ----
        float gxR0, gxZ0, gxNi0, gxR1, gxZ1, gxNi1;
        {
            const float* xb = x_s + cur * XBUF;
            const ulonglong2* x0 = reinterpret_cast<const ulonglong2*>(xb + b * XS + q * 32);
            const ulonglong2* x1 = reinterpret_cast<const ulonglong2*>(xb + (b + 4) * XS + q * 32);
            const ulonglong2* r0 = reinterpret_cast<const ulonglong2*>(wxR);
            const ulonglong2* r1 = reinterpret_cast<const ulonglong2*>(wxZ);
            const ulonglong2* r2 = reinterpret_cast<const ulonglong2*>(wxN);
            ull xR0 = 0, xZ0 = 0, xN0 = 0, xR1 = 0, xZ1 = 0, xN1 = 0;
            #pragma unroll 8
            for (int c = 0; c < 8; c++) {
                ulonglong2 v0 = r0[c], xv0 = x0[c], xv1 = x1[c];
                xR0 = ffma2(xv0.x, v0.x, xR0); xR0 = ffma2(xv0.y, v0.y, xR0);
                xR1 = ffma2(xv1.x, v0.x, xR1); xR1 = ffma2(xv1.y, v0.y, xR1);
                ulonglong2 v1 = r1[c];
                xZ0 = ffma2(xv0.x, v1.x, xZ0); xZ0 = ffma2(xv0.y, v1.y, xZ0);
                xZ1 = ffma2(xv1.x, v1.x, xZ1); xZ1 = ffma2(xv1.y, v1.y, xZ1);
                ulonglong2 v2 = r2[c];
                xN0 = ffma2(xv0.x, v2.x, xN0); xN0 = ffma2(xv0.y, v2.y, xN0);
                xN1 = ffma2(xv1.x, v2.x, xN1); xN1 = ffma2(xv1.y, v2.y, xN1);
            }
            gxR0 = sumf2(xR0); gxZ0 = sumf2(xZ0); gxNi0 = sumf2(xN0);
            gxR1 = sumf2(xR1); gxZ1 = sumf2(xZ1); gxNi1 = sumf2(xN1);
        }

        // ---- C: 7 pollers (own flag skipped), full barrier, stage ----
        if (t > 0) {
            if (tid < NSLICE && tid != slice) {
                while ((int)ld_acq(&g_hflag[fbase + tid]) < t) { }
            }
        }
        __syncthreads();                                   // S1
        if (t > 0) {
            float4 v = reinterpret_cast<const float4*>(g_h[cur])[(b0 + srow) * 64 + scol];
            *reinterpret_cast<float4*>(h_s + srow * HS + scol * 4) = v;
            const float* gp = g_yp[cur] + (b0 + srow) * 512 + scol;
            float s = fcb_s[scol];
            #pragma unroll
            for (int si = 0; si < 8; si++) s += gp[si * 64];
            y_s[srow * YS + scol] = tanhf(s);
        }
        __syncthreads();                                   // S2

        ull aR0 = 0, aR1 = 0, aZ0 = 0, aZ1 = 0;
        ull aNi0 = 0, aNi1 = 0, aNh0 = 0, aNh1 = 0;

        // ---- D: gh (quarter of K=256, 2 rows) ----
        {
            const ulonglong2* h0 = reinterpret_cast<const ulonglong2*>(h_s + b * HS + q * 64);
            const ulonglong2* h1 = reinterpret_cast<const ulonglong2*>(h_s + (b + 4) * HS + q * 64);
            const ulonglong2* r0 = reinterpret_cast<const ulonglong2*>(whR);
            const ulonglong2* r1 = reinterpret_cast<const ulonglong2*>(whZ);
            const ulonglong2* r2 = reinterpret_cast<const ulonglong2*>(whN);
            #pragma unroll 8
            for (int c = 0; c < 16; c++) {
                ulonglong2 v0 = r0[c], hv0 = h0[c], hv1 = h1[c];
                aR0 = ffma2(hv0.x, v0.x, aR0); aR0 = ffma2(hv0.y, v0.y, aR0);
                aR1 = ffma2(hv1.x, v0.x, aR1); aR1 = ffma2(hv1.y, v0.y, aR1);
                ulonglong2 v1 = r1[c];
                aZ0 = ffma2(hv0.x, v1.x, aZ0); aZ0 = ffma2(hv0.y, v1.y, aZ0);
                aZ1 = ffma2(hv1.x, v1.x, aZ1); aZ1 = ffma2(hv1.y, v1.y, aZ1);
                ulonglong2 v2 = r2[c];
                aNh0 = ffma2(hv0.x, v2.x, aNh0); aNh0 = ffma2(hv0.y, v2.y, aNh0);
                aNh1 = ffma2(hv1.x, v2.x, aNh1); aNh1 = ffma2(hv1.y, v2.y, aNh1);
            }
        }
        // ---- gi_y (quarter of O=64, 2 rows) ----
        {
            const ulonglong2* y0 = reinterpret_cast<const ulonglong2*>(y_s + b * YS + q * 16);
            const ulonglong2* y1 = reinterpret_cast<const ulonglong2*>(y_s + (b + 4) * YS + q * 16);
            const ulonglong2* r0 = reinterpret_cast<const ulonglong2*>(wyR);
            const ulonglong2* r1 = reinterpret_cast<const ulonglong2*>(wyZ);
            const ulonglong2* r2 = reinterpret_cast<const ulonglong2*>(wyN);
            #pragma unroll
            for (int c = 0; c < 4; c++) {
                ulonglong2 v0 = r0[c], yv0 = y0[c], yv1 = y1[c];
                aR0 = ffma2(yv0.x, v0.x, aR0); aR0 = ffma2(yv0.y, v0.y, aR0);
                aR1 = ffma2(yv1.x, v0.x, aR1); aR1 = ffma2(yv1.y, v0.y, aR1);
                ulonglong2 v1 = r1[c];
                aZ0 = ffma2(yv0.x, v1.x, aZ0); aZ0 = ffma2(yv0.y, v1.y, aZ0);
                aZ1 = ffma2(yv1.x, v1.x, aZ1); aZ1 = ffma2(yv1.y, v1.y, aZ1);
                ulonglong2 v2 = r2[c];
                aNi0 = ffma2(yv0.x, v2.x, aNi0); aNi0 = ffma2(yv0.y, v2.y, aNi0);
                aNi1 = ffma2(yv1.x, v2.x, aNi1); aNi1 = ffma2(yv1.y, v2.y, aNi1);
            }
        }

        // ---- E: partial store (q0, q2, q3); q1 combines ----
        if (q != 1) {
            int slot = (q == 0) ? 0 : (q - 1);
            p_s[slot * 256 + b * 32 + unit] =
                make_float4(sumf2(aR0) + gxR0, sumf2(aZ0) + gxZ0,
                            sumf2(aNi0) + gxNi0, sumf2(aNh0));
            p_s[slot * 256 + (b + 4) * 32 + unit] =
                make_float4(sumf2(aR1) + gxR1, sumf2(aZ1) + gxZ1,
                            sumf2(aNi1) + gxNi1, sumf2(aNh1));
        }
        __syncthreads();                                   // S3

        if (q == 1) {
            float4 s0 = make_float4(sumf2(aR0) + gxR0, sumf2(aZ0) + gxZ0,
                                    sumf2(aNi0) + gxNi0, sumf2(aNh0));
            float4 s1 = make_float4(sumf2(aR1) + gxR1, sumf2(aZ1) + gxZ1,
                                    sumf2(aNi1) + gxNi1, sumf2(aNh1));
            #pragma unroll
            for (int j = 0; j < 3; j++) {
                float4 pa = p_s[j * 256 + b * 32 + unit];
                float4 pb = p_s[j * 256 + (b + 4) * 32 + unit];
                s0.x += pa.x; s0.y += pa.y; s0.z += pa.z; s0.w += pa.w;
                s1.x += pb.x; s1.y += pb.y; s1.z += pb.z; s1.w += pb.w;
            }
            float biR = bih_s[unit] + bhh_s[unit];
            float biZ = bih_s[32 + unit] + bhh_s[32 + unit];
            float biN = bih_s[64 + unit];
            float bhN = bhh_s[64 + unit];

            float r0v = 1.0f / (1.0f + __expf(-(s0.x + biR)));
            float z0v = 1.0f / (1.0f + __expf(-(s0.y + biZ)));
            float n0v = tanhf(s0.z + biN + r0v * (s0.w + bhN));
            float hp0 = h_s[b * HS + slice * UNITS + unit];
            hstg_s[b * HSTG + unit] = (1.0f - z0v) * n0v + z0v * hp0;

            float r1v = 1.0f / (1.0f + __expf(-(s1.x + biR)));
            float z1v = 1.0f / (1.0f + __expf(-(s1.y + biZ)));
            float n1v = tanhf(s1.z + biN + r1v * (s1.w + bhN));
            float hp1 = h_s[(b + 4) * HS + slice * UNITS + unit];
            hstg_s[(b + 4) * HSTG + unit] = (1.0f - z1v) * n1v + z1v * hp1;
        }

        // ---- S4 narrowed: q1 (hstg writers) + readers (warps 0-3,10,11) ----
        if (in_s4) {
            barn(8, 320);

            // ---- G: publish hnew + fc partials; publisher-only tail ----
            if (is_pub) {
                if (tid < 64) {
                    int row = tid >> 3, cg = tid & 7;
                    float4 v = *reinterpret_cast<float4*>(hstg_s + row * HSTG + cg * 4);
                    reinterpret_cast<float4*>(g_h[nxt])[(b0 + row) * 64 + slice * 8 + cg] = v;
                }
                if (yo >= 0) {
                    const ulonglong2* fp = reinterpret_cast<const ulonglong2*>(fc2_s + yo * FST);
                    ulonglong2 fr[8];
                    #pragma unroll
                    for (int i = 0; i < 8; i++) fr[i] = fp[i];
                    #pragma unroll
                    for (int r = 0; r < 4; r++) {
                        const ulonglong2* hp =
                            reinterpret_cast<const ulonglong2*>(hstg_s + (rb + r) * HSTG);
                        ull a0 = 0, a1 = 0;
                        #pragma unroll
                        for (int i = 0; i < 8; i++) {
                            ulonglong2 hv = hp[i];
                            a0 = ffma2(hv.x, fr[i].x, a0);
                            a1 = ffma2(hv.y, fr[i].y, a1);
                        }
                        g_yp[nxt][(b0 + rb + r) * 512 + slice * 64 + yo] = sumf2(a0) + sumf2(a1);
                    }
                }
                barn(6, 192);                 // publishers: warps 0-3, 10, 11
                if (tid == 0) st_rel(&g_hflag[blk], (unsigned)(t + 1));
            }
        }
        // warps 8,9,12-15 skip S4 and the tail entirely
    }

    // ---- final: out = tanh(sum of fc partials of h_T + fcb) ----
    if (tid < NSLICE) { while ((int)ld_acq(&g_hflag[fbase + tid]) < TSTEPS) { } }
    __syncthreads();
    {
        const float* gp = g_yp[0] + (b0 + srow) * 512 + scol;  // T even -> buf 0
        float s = fcb_s[scol];
        #pragma unroll
        for (int si = 0; si < 8; si++) s += gp[si * 64];
        if ((scol >> 3) == slice)
            out[(b0 + srow) * OUTSZ + scol] = tanhf(s);
    }
}

extern "C" void kernel_launch(void* const* d_in, const int* in_sizes, int n_in,
                              void* d_out, int out_size) {
    (void)in_sizes; (void)n_in; (void)out_size;
    const float* x    = (const float*)d_in[0];
    const float* w_ih = (const float*)d_in[1];
    const float* w_hh = (const float*)d_in[2];
    const float* b_ih = (const float*)d_in[3];
    const float* b_hh = (const float*)d_in[4];
    const float* fc_w = (const float*)d_in[5];
    const float* fc_b = (const float*)d_in[6];
    float* out = (float*)d_out;

    const int smem_bytes = SMEM_FLOATS * (int)sizeof(float); // 217,792 B
    cudaFuncSetAttribute(jordan_kernel,
                         cudaFuncAttributeMaxDynamicSharedMemorySize,
                         smem_bytes);

    jordan_init_kernel<<<1, NBLK>>>();
    jordan_kernel<<<NBLK, NTHR, smem_bytes>>>(x, w_ih, w_hh, b_ih, b_hh,
                                              fc_w, fc_b, out);
}

// round 16
// speedup vs baseline: 1.2785x; 1.0405x over previous
#include <cuda_runtime.h>
#include <cstdint>
#include <cstddef>

// Jordan GRU, B=128, T=2048, I=128, H=256, O=64.
// 16 groups x 8 slices; CTA = 8 batch rows x 32 hidden units, 512 threads.
// Thread = (K-quarter q, unit, batch-pair) -> 2 rows per thread.
// Single exchange per step (hnew + fc partials under one release flag).
// R12 + deferred y-reduce: yp LDGs issued at C, consumed after gh, so the
// L2 latency drains under the gh compute.

#define TSTEPS 2048
#define INSZ 128
#define HID 256
#define OUTSZ 64
#define GIN 192
#define NBLK 128
#define NTHR 512
#define ROWS 8
#define UNITS 32
#define NSLICE 8

#define HS 260
#define XS 132
#define XBUF 1056     // one x buffer (8 * 132)
#define YS 68
#define WHS 260
#define WIS 196
#define FST 36
#define HSTG 36

// float offsets in dynamic smem
#define OFF_H    0                            // 8*260  = 2080
#define OFF_X    2080                         // 2*1056 = 2112
#define OFF_Y    4192                         // 8*68   = 544
#define OFF_P    4736                         // 3*256 float4 = 3072
#define OFF_HST  7808                         // 8*36   = 288
#define OFF_WHH  8096                         // 96*260 = 24960
#define OFF_WIH  33056                        // 96*196 = 18816
#define OFF_FC2  51872                        // 64*36  = 2304
#define OFF_BIH  54176                        // 96
#define OFF_BHH  54272                        // 96
#define OFF_FCB  54368                        // 64
#define SMEM_FLOATS 54448                     // 217,792 B

typedef unsigned long long ull;

__device__ float g_h[2][128 * HID];           // [buf][b][k]
__device__ float g_yp[2][128 * 512];          // [buf][b][slice][o]
__device__ unsigned g_hflag[NBLK];

__device__ __forceinline__ ull ffma2(ull a, ull b, ull c) {
    ull d; asm("fma.rn.f32x2 %0, %1, %2, %3;" : "=l"(d) : "l"(a), "l"(b), "l"(c));
    return d;
}
__device__ __forceinline__ float sumf2(ull v) {
    float a, b; asm("mov.b64 {%0, %1}, %2;" : "=f"(a), "=f"(b) : "l"(v));
    return a + b;
}
__device__ __forceinline__ unsigned ld_acq(const unsigned* p) {
    unsigned v; asm volatile("ld.acquire.gpu.global.u32 %0, [%1];" : "=r"(v) : "l"(p));
    return v;
}
__device__ __forceinline__ void st_rel(unsigned* p, unsigned v) {
    asm volatile("st.release.gpu.global.u32 [%0], %1;" :: "l"(p), "r"(v));
}
__device__ __forceinline__ void barn(int id, int cnt) {
    asm volatile("bar.sync %0, %1;" :: "r"(id), "r"(cnt) : "memory");
}

__global__ void jordan_init_kernel() {
    int i = blockIdx.x * blockDim.x + threadIdx.x;
    if (i < NBLK) g_hflag[i] = 0u;
}

__global__ void __launch_bounds__(NTHR, 1) jordan_kernel(
    const float* __restrict__ x,      // [B, T, I]
    const float* __restrict__ w_ih,   // [3H, GIN]
    const float* __restrict__ w_hh,   // [3H, H]
    const float* __restrict__ b_ih,   // [3H]
    const float* __restrict__ b_hh,   // [3H]
    const float* __restrict__ fc_w,   // [O, H]
    const float* __restrict__ fc_b,   // [O]
    float* __restrict__ out)          // [B, O]
{
    extern __shared__ float sm[];
    float*  h_s    = sm + OFF_H;
    float*  x_s    = sm + OFF_X;      // [2][8][XS]
    float*  y_s    = sm + OFF_Y;
    float4* p_s    = reinterpret_cast<float4*>(sm + OFF_P);
    float*  hstg_s = sm + OFF_HST;
    float*  whh_s  = sm + OFF_WHH;
    float*  wih_s  = sm + OFF_WIH;
    float*  fc2_s  = sm + OFF_FC2;
    float*  bih_s  = sm + OFF_BIH;
    float*  bhh_s  = sm + OFF_BHH;
    float*  fcb_s  = sm + OFF_FCB;

    const int tid  = threadIdx.x;
    const int q    = tid >> 7;          // K-quarter 0..3
    const int wg   = tid & 127;
    const int unit = wg >> 2;           // 0..31
    const int b    = wg & 3;            // rows b and b+4

    const int blk   = blockIdx.x;
    const int group = blk >> 3;
    const int slice = blk & 7;
    const int b0    = group * ROWS;
    const int fbase = group * NSLICE;

    // y-partial workers: warps 2,3 (rows 0-3) and 10,11 (rows 4-7)
    int yo = -1, rb = 0;
    if (tid >= 64 && tid < 128)        { yo = tid - 64;  rb = 0; }
    else if (tid >= 320 && tid < 384)  { yo = tid - 320; rb = 4; }

    // publisher set: warps 0-3 (h writers + ypart rows 0-3) and 10,11
    const bool is_pub = (tid < 128) || (tid >= 320 && tid < 384);

    // ---- load weights / biases, zero state ----
    for (int i = tid; i < 96 * HID; i += NTHR) {
        int row = i >> 8, k = i & 255;
        whh_s[row * WHS + k] =
            w_hh[((row >> 5) * HID + slice * UNITS + (row & 31)) * HID + k];
    }
    for (int i = tid; i < 96 * GIN; i += NTHR) {
        int row = i / GIN, k = i - row * GIN;
        wih_s[row * WIS + k] =
            w_ih[((row >> 5) * HID + slice * UNITS + (row & 31)) * GIN + k];
    }
    for (int i = tid; i < OUTSZ * 32; i += NTHR) {
        int o = i >> 5, k = i & 31;
        fc2_s[o * FST + k] = fc_w[o * HID + slice * 32 + k];
    }
    if (tid < 96) {
        int grow = (tid >> 5) * HID + slice * UNITS + (tid & 31);
        bih_s[tid] = b_ih[grow];
        bhh_s[tid] = b_hh[grow];
    }
    if (tid < 64) fcb_s[tid] = fc_b[tid];
    for (int i = tid; i < ROWS * HS; i += NTHR) h_s[i] = 0.0f;
    for (int i = tid; i < ROWS * YS; i += NTHR) y_s[i] = 0.0f;

    // stage x_0 into buffer 0, prefetch x_1
    float4 xreg;
    if (tid < 256) {
        int row = tid >> 5, c = tid & 31;
        float4 v0 = reinterpret_cast<const float4*>(x)
                        [((size_t)(b0 + row) * TSTEPS) * 32 + c];
        *reinterpret_cast<float4*>(x_s + row * XS + c * 4) = v0;
        xreg = reinterpret_cast<const float4*>(x)
                   [((size_t)(b0 + row) * TSTEPS + 1) * 32 + c];
    }
    __syncthreads();

    const float* whR = whh_s + (0 * UNITS + unit) * WHS + q * 64;
    const float* whZ = whh_s + (1 * UNITS + unit) * WHS + q * 64;
    const float* whN = whh_s + (2 * UNITS + unit) * WHS + q * 64;
    const float* wxR = wih_s + (0 * UNITS + unit) * WIS + q * 32;
    const float* wxZ = wih_s + (1 * UNITS + unit) * WIS + q * 32;
    const float* wxN = wih_s + (2 * UNITS + unit) * WIS + q * 32;
    const float* wyR = wih_s + (0 * UNITS + unit) * WIS + INSZ + q * 16;
    const float* wyZ = wih_s + (1 * UNITS + unit) * WIS + INSZ + q * 16;
    const float* wyN = wih_s + (2 * UNITS + unit) * WIS + INSZ + q * 16;

    const int srow = tid >> 6;           // staging row 0..7
    const int scol = tid & 63;           // staging col / output index

    for (int t = 0; t < TSTEPS; t++) {
        const int cur = t & 1, nxt = cur ^ 1;

        // ---- A: store x_{t+1} into xbuf[nxt]; prefetch x_{t+2} ----
        if (tid < 256 && t + 1 < TSTEPS) {
            int row = tid >> 5, c = tid & 31;
            *reinterpret_cast<float4*>(x_s + nxt * XBUF + row * XS + c * 4) = xreg;
            if (t + 2 < TSTEPS)
                xreg = reinterpret_cast<const float4*>(x)
                           [((size_t)(b0 + row) * TSTEPS + t + 2) * 32 + c];
        }

        // ---- B: gi_x hoisted (independent of recurrence) ----
        float gxR0, gxZ0, gxNi0, gxR1, gxZ1, gxNi1;
        {
            const float* xb = x_s + cur * XBUF;
            const ulonglong2* x0 = reinterpret_cast<const ulonglong2*>(xb + b * XS + q * 32);
            const ulonglong2* x1 = reinterpret_cast<const ulonglong2*>(xb + (b + 4) * XS + q * 32);
            const ulonglong2* r0 = reinterpret_cast<const ulonglong2*>(wxR);
            const ulonglong2* r1 = reinterpret_cast<const ulonglong2*>(wxZ);
            const ulonglong2* r2 = reinterpret_cast<const ulonglong2*>(wxN);
            ull xR0 = 0, xZ0 = 0, xN0 = 0, xR1 = 0, xZ1 = 0, xN1 = 0;
            #pragma unroll 8
            for (int c = 0; c < 8; c++) {
                ulonglong2 v0 = r0[c], xv0 = x0[c], xv1 = x1[c];
                xR0 = ffma2(xv0.x, v0.x, xR0); xR0 = ffma2(xv0.y, v0.y, xR0);
                xR1 = ffma2(xv1.x, v0.x, xR1); xR1 = ffma2(xv1.y, v0.y, xR1);
                ulonglong2 v1 = r1[c];
                xZ0 = ffma2(xv0.x, v1.x, xZ0); xZ0 = ffma2(xv0.y, v1.y, xZ0);
                xZ1 = ffma2(xv1.x, v1.x, xZ1); xZ1 = ffma2(xv1.y, v1.y, xZ1);
                ulonglong2 v2 = r2[c];
                xN0 = ffma2(xv0.x, v2.x, xN0); xN0 = ffma2(xv0.y, v2.y, xN0);
                xN1 = ffma2(xv1.x, v2.x, xN1); xN1 = ffma2(xv1.y, v2.y, xN1);
            }
            gxR0 = sumf2(xR0); gxZ0 = sumf2(xZ0); gxNi0 = sumf2(xN0);
            gxR1 = sumf2(xR1); gxZ1 = sumf2(xZ1); gxNi1 = sumf2(xN1);
        }

        // ---- C: 8 pollers, barrier, stage h + ISSUE yp loads (no reduce) ----
        float ypr0, ypr1, ypr2, ypr3, ypr4, ypr5, ypr6, ypr7;
        if (t > 0) {
            if (tid < NSLICE) { while ((int)ld_acq(&g_hflag[fbase + tid]) < t) { } }
        }
        __syncthreads();                                   // S1
        if (t > 0) {
            float4 v = reinterpret_cast<const float4*>(g_h[cur])[(b0 + srow) * 64 + scol];
            *reinterpret_cast<float4*>(h_s + srow * HS + scol * 4) = v;
            const float* gp = g_yp[cur] + (b0 + srow) * 512 + scol;
            ypr0 = gp[0 * 64]; ypr1 = gp[1 * 64];
            ypr2 = gp[2 * 64]; ypr3 = gp[3 * 64];
            ypr4 = gp[4 * 64]; ypr5 = gp[5 * 64];
            ypr6 = gp[6 * 64]; ypr7 = gp[7 * 64];
        }
        __syncthreads();                                   // S2 (h_s ready)

        ull aR0 = 0, aR1 = 0, aZ0 = 0, aZ1 = 0;
        ull aNi0 = 0, aNi1 = 0, aNh0 = 0, aNh1 = 0;

        // ---- D: gh (quarter of K=256, 2 rows); yp latency drains here ----
        {
            const ulonglong2* h0 = reinterpret_cast<const ulonglong2*>(h_s + b * HS + q * 64);
            const ulonglong2* h1 = reinterpret_cast<const ulonglong2*>(h_s + (b + 4) * HS + q * 64);
            const ulonglong2* r0 = reinterpret_cast<const ulonglong2*>(whR);
            const ulonglong2* r1 = reinterpret_cast<const ulonglong2*>(whZ);
            const ulonglong2* r2 = reinterpret_cast<const ulonglong2*>(whN);
            #pragma unroll 8
            for (int c = 0; c < 16; c++) {
                ulonglong2 v0 = r0[c], hv0 = h0[c], hv1 = h1[c];
                aR0 = ffma2(hv0.x, v0.x, aR0); aR0 = ffma2(hv0.y, v0.y, aR0);
                aR1 = ffma2(hv1.x, v0.x, aR1); aR1 = ffma2(hv1.y, v0.y, aR1);
                ulonglong2 v1 = r1[c];
                aZ0 = ffma2(hv0.x, v1.x, aZ0); aZ0 = ffma2(hv0.y, v1.y, aZ0);
                aZ1 = ffma2(hv1.x, v1.x, aZ1); aZ1 = ffma2(hv1.y, v1.y, aZ1);
                ulonglong2 v2 = r2[c];
                aNh0 = ffma2(hv0.x, v2.x, aNh0); aNh0 = ffma2(hv0.y, v2.y, aNh0);
                aNh1 = ffma2(hv1.x, v2.x, aNh1); aNh1 = ffma2(hv1.y, v2.y, aNh1);
            }
        }

        // ---- finalize y_t from yp registers (post-gh), then sync ----
        if (t > 0) {
            float s = fcb_s[scol] + ypr0 + ypr1 + ypr2 + ypr3
                                  + ypr4 + ypr5 + ypr6 + ypr7;
            y_s[srow * YS + scol] = tanhf(s);
            __syncthreads();                               // S2b (y_s ready)
        }

        // ---- gi_y (quarter of O=64, 2 rows) ----
        {
            const ulonglong2* y0 = reinterpret_cast<const ulonglong2*>(y_s + b * YS + q * 16);
            const ulonglong2* y1 = reinterpret_cast<const ulonglong2*>(y_s + (b + 4) * YS + q * 16);
            const ulonglong2* r0 = reinterpret_cast<const ulonglong2*>(wyR);
            const ulonglong2* r1 = reinterpret_cast<const ulonglong2*>(wyZ);
            const ulonglong2* r2 = reinterpret_cast<const ulonglong2*>(wyN);
            #pragma unroll
            for (int c = 0; c < 4; c++) {
                ulonglong2 v0 = r0[c], yv0 = y0[c], yv1 = y1[c];
                aR0 = ffma2(yv0.x, v0.x, aR0); aR0 = ffma2(yv0.y, v0.y, aR0);
                aR1 = ffma2(yv1.x, v0.x, aR1); aR1 = ffma2(yv1.y, v0.y, aR1);
                ulonglong2 v1 = r1[c];
                aZ0 = ffma2(yv0.x, v1.x, aZ0); aZ0 = ffma2(yv0.y, v1.y, aZ0);
                aZ1 = ffma2(yv1.x, v1.x, aZ1); aZ1 = ffma2(yv1.y, v1.y, aZ1);
                ulonglong2 v2 = r2[c];
                aNi0 = ffma2(yv0.x, v2.x, aNi0); aNi0 = ffma2(yv0.y, v2.y, aNi0);
                aNi1 = ffma2(yv1.x, v2.x, aNi1); aNi1 = ffma2(yv1.y, v2.y, aNi1);
            }
        }

        // ---- E: partial store (q0, q2, q3); q1 combines ----
        if (q != 1) {
            int slot = (q == 0) ? 0 : (q - 1);
            p_s[slot * 256 + b * 32 + unit] =
                make_float4(sumf2(aR0) + gxR0, sumf2(aZ0) + gxZ0,
                            sumf2(aNi0) + gxNi0, sumf2(aNh0));
            p_s[slot * 256 + (b + 4) * 32 + unit] =
                make_float4(sumf2(aR1) + gxR1, sumf2(aZ1) + gxZ1,
                            sumf2(aNi1) + gxNi1, sumf2(aNh1));
        }
        __syncthreads();                                   // S3

        if (q == 1) {
            float4 s0 = make_float4(sumf2(aR0) + gxR0, sumf2(aZ0) + gxZ0,
                                    sumf2(aNi0) + gxNi0, sumf2(aNh0));
            float4 s1 = make_float4(sumf2(aR1) + gxR1, sumf2(aZ1) + gxZ1,
                                    sumf2(aNi1) + gxNi1, sumf2(aNh1));
            #pragma unroll
            for (int j = 0; j < 3; j++) {
                float4 pa = p_s[j * 256 + b * 32 + unit];
                float4 pb = p_s[j * 256 + (b + 4) * 32 + unit];
                s0.x += pa.x; s0.y += pa.y; s0.z += pa.z; s0.w += pa.w;
                s1.x += pb.x; s1.y += pb.y; s1.z += pb.z; s1.w += pb.w;
            }
            float biR = bih_s[unit] + bhh_s[unit];
            float biZ = bih_s[32 + unit] + bhh_s[32 + unit];
            float biN = bih_s[64 + unit];
            float bhN = bhh_s[64 + unit];

            float r0v = 1.0f / (1.0f + __expf(-(s0.x + biR)));
            float z0v = 1.0f / (1.0f + __expf(-(s0.y + biZ)));
            float n0v = tanhf(s0.z + biN + r0v * (s0.w + bhN));
            float hp0 = h_s[b * HS + slice * UNITS + unit];
            hstg_s[b * HSTG + unit] = (1.0f - z0v) * n0v + z0v * hp0;

            float r1v = 1.0f / (1.0f + __expf(-(s1.x + biR)));
            float z1v = 1.0f / (1.0f + __expf(-(s1.y + biZ)));
            float n1v = tanhf(s1.z + biN + r1v * (s1.w + bhN));
            float hp1 = h_s[(b + 4) * HS + slice * UNITS + unit];
            hstg_s[(b + 4) * HSTG + unit] = (1.0f - z1v) * n1v + z1v * hp1;
        }
        __syncthreads();                                   // S4

        // ---- G: publish hnew + fc partials; publisher-only tail ----
        if (is_pub) {
            if (tid < 64) {
                int row = tid >> 3, cg = tid & 7;
                float4 v = *reinterpret_cast<float4*>(hstg_s + row * HSTG + cg * 4);
                reinterpret_cast<float4*>(g_h[nxt])[(b0 + row) * 64 + slice * 8 + cg] = v;
            }
            if (yo >= 0) {
                const ulonglong2* fp = reinterpret_cast<const ulonglong2*>(fc2_s + yo * FST);
                ulonglong2 fr[8];
                #pragma unroll
                for (int i = 0; i < 8; i++) fr[i] = fp[i];
                #pragma unroll
                for (int r = 0; r < 4; r++) {
                    const ulonglong2* hp =
                        reinterpret_cast<const ulonglong2*>(hstg_s + (rb + r) * HSTG);
                    ull a0 = 0, a1 = 0;
                    #pragma unroll
                    for (int i = 0; i < 8; i++) {
                        ulonglong2 hv = hp[i];
                        a0 = ffma2(hv.x, fr[i].x, a0);
                        a1 = ffma2(hv.y, fr[i].y, a1);
                    }
                    g_yp[nxt][(b0 + rb + r) * 512 + slice * 64 + yo] = sumf2(a0) + sumf2(a1);
                }
            }
            barn(6, 192);                 // publishers: warps 0-3, 10, 11
            if (tid == 0) st_rel(&g_hflag[blk], (unsigned)(t + 1));
        }
        // non-publishers fall through to next step's A/B immediately
    }

    // ---- final: out = tanh(sum of fc partials of h_T + fcb) ----
    if (tid < NSLICE) { while ((int)ld_acq(&g_hflag[fbase + tid]) < TSTEPS) { } }
    __syncthreads();
    {
        const float* gp = g_yp[0] + (b0 + srow) * 512 + scol;  // T even -> buf 0
        float s = fcb_s[scol];
        #pragma unroll
        for (int si = 0; si < 8; si++) s += gp[si * 64];
        if ((scol >> 3) == slice)
            out[(b0 + srow) * OUTSZ + scol] = tanhf(s);
    }
}

extern "C" void kernel_launch(void* const* d_in, const int* in_sizes, int n_in,
                              void* d_out, int out_size) {
    (void)in_sizes; (void)n_in; (void)out_size;
    const float* x    = (const float*)d_in[0];
    const float* w_ih = (const float*)d_in[1];
    const float* w_hh = (const float*)d_in[2];
    const float* b_ih = (const float*)d_in[3];
    const float* b_hh = (const float*)d_in[4];
    const float* fc_w = (const float*)d_in[5];
    const float* fc_b = (const float*)d_in[6];
    float* out = (float*)d_out;

    const int smem_bytes = SMEM_FLOATS * (int)sizeof(float); // 217,792 B
    cudaFuncSetAttribute(jordan_kernel,
                         cudaFuncAttributeMaxDynamicSharedMemorySize,
                         smem_bytes);

    jordan_init_kernel<<<1, NBLK>>>();
    jordan_kernel<<<NBLK, NTHR, smem_bytes>>>(x, w_ih, w_hh, b_ih, b_hh,
                                              fc_w, fc_b, out);
}

// round 17
// speedup vs baseline: 1.3300x; 1.0403x over previous
#include <cuda_runtime.h>
#include <cstdint>
#include <cstddef>

// Jordan GRU, B=128, T=2048, I=128, H=256, O=64.
// 16 groups x 8 slices; CTA = 8 batch rows x 32 hidden units, 512 threads.
// Thread = (K-quarter q, unit, batch-pair) -> 2 rows per thread.
// Single exchange per step (hnew + fc partials under one release flag).
// R16 + combine/gates spread over q0+q1 (1 row per thread) + own-flag skip.

#define TSTEPS 2048
#define INSZ 128
#define HID 256
#define OUTSZ 64
#define GIN 192
#define NBLK 128
#define NTHR 512
#define ROWS 8
#define UNITS 32
#define NSLICE 8

#define HS 260
#define XS 132
#define XBUF 1056     // one x buffer (8 * 132)
#define YS 68
#define WHS 260
#define WIS 196
#define FST 36
#define HSTG 36
#define PSTR 33       // p_s row stride in float4 (pad kills bank conflicts)
#define PSLOT (8 * PSTR)   // 264 float4 per quarter slot

// float offsets in dynamic smem
#define OFF_H    0                            // 8*260  = 2080
#define OFF_X    2080                         // 2*1056 = 2112
#define OFF_Y    4192                         // 8*68   = 544
#define OFF_P    4736                         // 4*264 float4 = 4224 floats
#define OFF_HST  8960                         // 8*36   = 288
#define OFF_WHH  9248                         // 96*260 = 24960
#define OFF_WIH  34208                        // 96*196 = 18816
#define OFF_FC2  53024                        // 64*36  = 2304
#define OFF_BIH  55328                        // 96
#define OFF_BHH  55424                        // 96
#define OFF_FCB  55520                        // 64
#define SMEM_FLOATS 55584                     // 222,336 B

typedef unsigned long long ull;

__device__ float g_h[2][128 * HID];           // [buf][b][k]
__device__ float g_yp[2][128 * 512];          // [buf][b][slice][o]
__device__ unsigned g_hflag[NBLK];

__device__ __forceinline__ ull ffma2(ull a, ull b, ull c) {
    ull d; asm("fma.rn.f32x2 %0, %1, %2, %3;" : "=l"(d) : "l"(a), "l"(b), "l"(c));
    return d;
}
__device__ __forceinline__ float sumf2(ull v) {
    float a, b; asm("mov.b64 {%0, %1}, %2;" : "=f"(a), "=f"(b) : "l"(v));
    return a + b;
}
__device__ __forceinline__ unsigned ld_acq(const unsigned* p) {
    unsigned v; asm volatile("ld.acquire.gpu.global.u32 %0, [%1];" : "=r"(v) : "l"(p));
    return v;
}
__device__ __forceinline__ void st_rel(unsigned* p, unsigned v) {
    asm volatile("st.release.gpu.global.u32 [%0], %1;" :: "l"(p), "r"(v));
}
__device__ __forceinline__ void barn(int id, int cnt) {
    asm volatile("bar.sync %0, %1;" :: "r"(id), "r"(cnt) : "memory");
}

__global__ void jordan_init_kernel() {
    int i = blockIdx.x * blockDim.x + threadIdx.x;
    if (i < NBLK) g_hflag[i] = 0u;
}

__global__ void __launch_bounds__(NTHR, 1) jordan_kernel(
    const float* __restrict__ x,      // [B, T, I]
    const float* __restrict__ w_ih,   // [3H, GIN]
    const float* __restrict__ w_hh,   // [3H, H]
    const float* __restrict__ b_ih,   // [3H]
    const float* __restrict__ b_hh,   // [3H]
    const float* __restrict__ fc_w,   // [O, H]
    const float* __restrict__ fc_b,   // [O]
    float* __restrict__ out)          // [B, O]
{
    extern __shared__ float sm[];
    float*  h_s    = sm + OFF_H;
    float*  x_s    = sm + OFF_X;      // [2][8][XS]
    float*  y_s    = sm + OFF_Y;
    float4* p_s    = reinterpret_cast<float4*>(sm + OFF_P);   // 4 slots
    float*  hstg_s = sm + OFF_HST;
    float*  whh_s  = sm + OFF_WHH;
    float*  wih_s  = sm + OFF_WIH;
    float*  fc2_s  = sm + OFF_FC2;
    float*  bih_s  = sm + OFF_BIH;
    float*  bhh_s  = sm + OFF_BHH;
    float*  fcb_s  = sm + OFF_FCB;

    const int tid  = threadIdx.x;
    const int q    = tid >> 7;          // K-quarter 0..3
    const int wg   = tid & 127;
    const int unit = wg >> 2;           // 0..31
    const int b    = wg & 3;            // rows b and b+4

    const int blk   = blockIdx.x;
    const int group = blk >> 3;
    const int slice = blk & 7;
    const int b0    = group * ROWS;
    const int fbase = group * NSLICE;

    // y-partial workers: warps 2,3 (rows 0-3) and 10,11 (rows 4-7)
    int yo = -1, rb = 0;
    if (tid >= 64 && tid < 128)        { yo = tid - 64;  rb = 0; }
    else if (tid >= 320 && tid < 384)  { yo = tid - 320; rb = 4; }

    // publisher set: warps 0-3 (h writers + ypart rows 0-3) and 10,11
    const bool is_pub = (tid < 128) || (tid >= 320 && tid < 384);

    // ---- load weights / biases, zero state ----
    for (int i = tid; i < 96 * HID; i += NTHR) {
        int row = i >> 8, k = i & 255;
        whh_s[row * WHS + k] =
            w_hh[((row >> 5) * HID + slice * UNITS + (row & 31)) * HID + k];
    }
    for (int i = tid; i < 96 * GIN; i += NTHR) {
        int row = i / GIN, k = i - row * GIN;
        wih_s[row * WIS + k] =
            w_ih[((row >> 5) * HID + slice * UNITS + (row & 31)) * GIN + k];
    }
    for (int i = tid; i < OUTSZ * 32; i += NTHR) {
        int o = i >> 5, k = i & 31;
        fc2_s[o * FST + k] = fc_w[o * HID + slice * 32 + k];
    }
    if (tid < 96) {
        int grow = (tid >> 5) * HID + slice * UNITS + (tid & 31);
        bih_s[tid] = b_ih[grow];
        bhh_s[tid] = b_hh[grow];
    }
    if (tid < 64) fcb_s[tid] = fc_b[tid];
    for (int i = tid; i < ROWS * HS; i += NTHR) h_s[i] = 0.0f;
    for (int i = tid; i < ROWS * YS; i += NTHR) y_s[i] = 0.0f;

    // stage x_0 into buffer 0, prefetch x_1
    float4 xreg;
    if (tid < 256) {
        int row = tid >> 5, c = tid & 31;
        float4 v0 = reinterpret_cast<const float4*>(x)
                        [((size_t)(b0 + row) * TSTEPS) * 32 + c];
        *reinterpret_cast<float4*>(x_s + row * XS + c * 4) = v0;
        xreg = reinterpret_cast<const float4*>(x)
                   [((size_t)(b0 + row) * TSTEPS + 1) * 32 + c];
    }
    __syncthreads();

    const float* whR = whh_s + (0 * UNITS + unit) * WHS + q * 64;
    const float* whZ = whh_s + (1 * UNITS + unit) * WHS + q * 64;
    const float* whN = whh_s + (2 * UNITS + unit) * WHS + q * 64;
    const float* wxR = wih_s + (0 * UNITS + unit) * WIS + q * 32;
    const float* wxZ = wih_s + (1 * UNITS + unit) * WIS + q * 32;
    const float* wxN = wih_s + (2 * UNITS + unit) * WIS + q * 32;
    const float* wyR = wih_s + (0 * UNITS + unit) * WIS + INSZ + q * 16;
    const float* wyZ = wih_s + (1 * UNITS + unit) * WIS + INSZ + q * 16;
    const float* wyN = wih_s + (2 * UNITS + unit) * WIS + INSZ + q * 16;

    const int srow = tid >> 6;           // staging row 0..7
    const int scol = tid & 63;           // staging col / output index
    const int crow = q * 4 + b;          // combine row for q < 2

    for (int t = 0; t < TSTEPS; t++) {
        const int cur = t & 1, nxt = cur ^ 1;

        // ---- A: store x_{t+1} into xbuf[nxt]; prefetch x_{t+2} ----
        if (tid < 256 && t + 1 < TSTEPS) {
            int row = tid >> 5, c = tid & 31;
            *reinterpret_cast<float4*>(x_s + nxt * XBUF + row * XS + c * 4) = xreg;
            if (t + 2 < TSTEPS)
                xreg = reinterpret_cast<const float4*>(x)
                           [((size_t)(b0 + row) * TSTEPS + t + 2) * 32 + c];
        }

        // ---- B: gi_x hoisted (independent of recurrence) ----
        float gxR0, gxZ0, gxNi0, gxR1, gxZ1, gxNi1;
        {
            const float* xb = x_s + cur * XBUF;
            const ulonglong2* x0 = reinterpret_cast<const ulonglong2*>(xb + b * XS + q * 32);
            const ulonglong2* x1 = reinterpret_cast<const ulonglong2*>(xb + (b + 4) * XS + q * 32);
            const ulonglong2* r0 = reinterpret_cast<const ulonglong2*>(wxR);
            const ulonglong2* r1 = reinterpret_cast<const ulonglong2*>(wxZ);
            const ulonglong2* r2 = reinterpret_cast<const ulonglong2*>(wxN);
            ull xR0 = 0, xZ0 = 0, xN0 = 0, xR1 = 0, xZ1 = 0, xN1 = 0;
            #pragma unroll 8
            for (int c = 0; c < 8; c++) {
                ulonglong2 v0 = r0[c], xv0 = x0[c], xv1 = x1[c];
                xR0 = ffma2(xv0.x, v0.x, xR0); xR0 = ffma2(xv0.y, v0.y, xR0);
                xR1 = ffma2(xv1.x, v0.x, xR1); xR1 = ffma2(xv1.y, v0.y, xR1);
                ulonglong2 v1 = r1[c];
                xZ0 = ffma2(xv0.x, v1.x, xZ0); xZ0 = ffma2(xv0.y, v1.y, xZ0);
                xZ1 = ffma2(xv1.x, v1.x, xZ1); xZ1 = ffma2(xv1.y, v1.y, xZ1);
                ulonglong2 v2 = r2[c];
                xN0 = ffma2(xv0.x, v2.x, xN0); xN0 = ffma2(xv0.y, v2.y, xN0);
                xN1 = ffma2(xv1.x, v2.x, xN1); xN1 = ffma2(xv1.y, v2.y, xN1);
            }
            gxR0 = sumf2(xR0); gxZ0 = sumf2(xZ0); gxNi0 = sumf2(xN0);
            gxR1 = sumf2(xR1); gxZ1 = sumf2(xZ1); gxNi1 = sumf2(xN1);
        }

        // ---- C: pollers (own flag skipped), barrier, stage h + yp loads ----
        float ypr0, ypr1, ypr2, ypr3, ypr4, ypr5, ypr6, ypr7;
        if (t > 0) {
            if (tid < NSLICE && tid != slice) {
                while ((int)ld_acq(&g_hflag[fbase + tid]) < t) { }
            }
        }
        __syncthreads();                                   // S1
        if (t > 0) {
            float4 v = reinterpret_cast<const float4*>(g_h[cur])[(b0 + srow) * 64 + scol];
            *reinterpret_cast<float4*>(h_s + srow * HS + scol * 4) = v;
            const float* gp = g_yp[cur] + (b0 + srow) * 512 + scol;
            ypr0 = gp[0 * 64]; ypr1 = gp[1 * 64];
            ypr2 = gp[2 * 64]; ypr3 = gp[3 * 64];
            ypr4 = gp[4 * 64]; ypr5 = gp[5 * 64];
            ypr6 = gp[6 * 64]; ypr7 = gp[7 * 64];
        }
        __syncthreads();                                   // S2 (h_s ready)

        ull aR0 = 0, aR1 = 0, aZ0 = 0, aZ1 = 0;
        ull aNi0 = 0, aNi1 = 0, aNh0 = 0, aNh1 = 0;

        // ---- D: gh (quarter of K=256, 2 rows); yp latency drains here ----
        {
            const ulonglong2* h0 = reinterpret_cast<const ulonglong2*>(h_s + b * HS + q * 64);
            const ulonglong2* h1 = reinterpret_cast<const ulonglong2*>(h_s + (b + 4) * HS + q * 64);
            const ulonglong2* r0 = reinterpret_cast<const ulonglong2*>(whR);
            const ulonglong2* r1 = reinterpret_cast<const ulonglong2*>(whZ);
            const ulonglong2* r2 = reinterpret_cast<const ulonglong2*>(whN);
            #pragma unroll 8
            for (int c = 0; c < 16; c++) {
                ulonglong2 v0 = r0[c], hv0 = h0[c], hv1 = h1[c];
                aR0 = ffma2(hv0.x, v0.x, aR0); aR0 = ffma2(hv0.y, v0.y, aR0);
                aR1 = ffma2(hv1.x, v0.x, aR1); aR1 = ffma2(hv1.y, v0.y, aR1);
                ulonglong2 v1 = r1[c];
                aZ0 = ffma2(hv0.x, v1.x, aZ0); aZ0 = ffma2(hv0.y, v1.y, aZ0);
                aZ1 = ffma2(hv1.x, v1.x, aZ1); aZ1 = ffma2(hv1.y, v1.y, aZ1);
                ulonglong2 v2 = r2[c];
                aNh0 = ffma2(hv0.x, v2.x, aNh0); aNh0 = ffma2(hv0.y, v2.y, aNh0);
                aNh1 = ffma2(hv1.x, v2.x, aNh1); aNh1 = ffma2(hv1.y, v2.y, aNh1);
            }
        }

        // ---- finalize y_t from yp registers (post-gh), then sync ----
        if (t > 0) {
            float s = fcb_s[scol] + ypr0 + ypr1 + ypr2 + ypr3
                                  + ypr4 + ypr5 + ypr6 + ypr7;
            y_s[srow * YS + scol] = tanhf(s);
            __syncthreads();                               // S2b (y_s ready)
        }

        // ---- gi_y (quarter of O=64, 2 rows) ----
        {
            const ulonglong2* y0 = reinterpret_cast<const ulonglong2*>(y_s + b * YS + q * 16);
            const ulonglong2* y1 = reinterpret_cast<const ulonglong2*>(y_s + (b + 4) * YS + q * 16);
            const ulonglong2* r0 = reinterpret_cast<const ulonglong2*>(wyR);
            const ulonglong2* r1 = reinterpret_cast<const ulonglong2*>(wyZ);
            const ulonglong2* r2 = reinterpret_cast<const ulonglong2*>(wyN);
            #pragma unroll
            for (int c = 0; c < 4; c++) {
                ulonglong2 v0 = r0[c], yv0 = y0[c], yv1 = y1[c];
                aR0 = ffma2(yv0.x, v0.x, aR0); aR0 = ffma2(yv0.y, v0.y, aR0);
                aR1 = ffma2(yv1.x, v0.x, aR1); aR1 = ffma2(yv1.y, v0.y, aR1);
                ulonglong2 v1 = r1[c];
                aZ0 = ffma2(yv0.x, v1.x, aZ0); aZ0 = ffma2(yv0.y, v1.y, aZ0);
                aZ1 = ffma2(yv1.x, v1.x, aZ1); aZ1 = ffma2(yv1.y, v1.y, aZ1);
                ulonglong2 v2 = r2[c];
                aNi0 = ffma2(yv0.x, v2.x, aNi0); aNi0 = ffma2(yv0.y, v2.y, aNi0);
                aNi1 = ffma2(yv1.x, v2.x, aNi1); aNi1 = ffma2(yv1.y, v2.y, aNi1);
            }
        }

        // ---- E: ALL quarters store partials (slot q, padded rows) ----
        p_s[q * PSLOT + b * PSTR + unit] =
            make_float4(sumf2(aR0) + gxR0, sumf2(aZ0) + gxZ0,
                        sumf2(aNi0) + gxNi0, sumf2(aNh0));
        p_s[q * PSLOT + (b + 4) * PSTR + unit] =
            make_float4(sumf2(aR1) + gxR1, sumf2(aZ1) + gxZ1,
                        sumf2(aNi1) + gxNi1, sumf2(aNh1));
        __syncthreads();                                   // S3

        // ---- F: combine + gates, 1 row per thread (q0 -> 0-3, q1 -> 4-7) ----
        if (q < 2) {
            float4 s0 = p_s[0 * PSLOT + crow * PSTR + unit];
            #pragma unroll
            for (int j = 1; j < 4; j++) {
                float4 pa = p_s[j * PSLOT + crow * PSTR + unit];
                s0.x += pa.x; s0.y += pa.y; s0.z += pa.z; s0.w += pa.w;
            }
            float biR = bih_s[unit] + bhh_s[unit];
            float biZ = bih_s[32 + unit] + bhh_s[32 + unit];
            float biN = bih_s[64 + unit];
            float bhN = bhh_s[64 + unit];

            float rv = 1.0f / (1.0f + __expf(-(s0.x + biR)));
            float zv = 1.0f / (1.0f + __expf(-(s0.y + biZ)));
            float nv = tanhf(s0.z + biN + rv * (s0.w + bhN));
            float hp = h_s[crow * HS + slice * UNITS + unit];
            hstg_s[crow * HSTG + unit] = (1.0f - zv) * nv + zv * hp;
        }
        __syncthreads();                                   // S4

        // ---- G: publish hnew + fc partials; publisher-only tail ----
        if (is_pub) {
            if (tid < 64) {
                int row = tid >> 3, cg = tid & 7;
                float4 v = *reinterpret_cast<float4*>(hstg_s + row * HSTG + cg * 4);
                reinterpret_cast<float4*>(g_h[nxt])[(b0 + row) * 64 + slice * 8 + cg] = v;
            }
            if (yo >= 0) {
                const ulonglong2* fp = reinterpret_cast<const ulonglong2*>(fc2_s + yo * FST);
                ulonglong2 fr[8];
                #pragma unroll
                for (int i = 0; i < 8; i++) fr[i] = fp[i];
                #pragma unroll
                for (int r = 0; r < 4; r++) {
                    const ulonglong2* hp =
                        reinterpret_cast<const ulonglong2*>(hstg_s + (rb + r) * HSTG);
                    ull a0 = 0, a1 = 0;
                    #pragma unroll
                    for (int i = 0; i < 8; i++) {
                        ulonglong2 hv = hp[i];
                        a0 = ffma2(hv.x, fr[i].x, a0);
                        a1 = ffma2(hv.y, fr[i].y, a1);
                    }
                    g_yp[nxt][(b0 + rb + r) * 512 + slice * 64 + yo] = sumf2(a0) + sumf2(a1);
                }
            }
            barn(6, 192);                 // publishers: warps 0-3, 10, 11
            if (tid == 0) st_rel(&g_hflag[blk], (unsigned)(t + 1));
        }
        // non-publishers fall through to next step's A/B immediately
    }

    // ---- final: out = tanh(sum of fc partials of h_T + fcb) ----
    if (tid < NSLICE) { while ((int)ld_acq(&g_hflag[fbase + tid]) < TSTEPS) { } }
    __syncthreads();
    {
        const float* gp = g_yp[0] + (b0 + srow) * 512 + scol;  // T even -> buf 0
        float s = fcb_s[scol];
        #pragma unroll
        for (int si = 0; si < 8; si++) s += gp[si * 64];
        if ((scol >> 3) == slice)
            out[(b0 + srow) * OUTSZ + scol] = tanhf(s);
    }
}

extern "C" void kernel_launch(void* const* d_in, const int* in_sizes, int n_in,
                              void* d_out, int out_size) {
    (void)in_sizes; (void)n_in; (void)out_size;
    const float* x    = (const float*)d_in[0];
    const float* w_ih = (const float*)d_in[1];
    const float* w_hh = (const float*)d_in[2];
    const float* b_ih = (const float*)d_in[3];
    const float* b_hh = (const float*)d_in[4];
    const float* fc_w = (const float*)d_in[5];
    const float* fc_b = (const float*)d_in[6];
    float* out = (float*)d_out;

    const int smem_bytes = SMEM_FLOATS * (int)sizeof(float); // 222,336 B
    cudaFuncSetAttribute(jordan_kernel,
                         cudaFuncAttributeMaxDynamicSharedMemorySize,
                         smem_bytes);

    jordan_init_kernel<<<1, NBLK>>>();
    jordan_kernel<<<NBLK, NTHR, smem_bytes>>>(x, w_ih, w_hh, b_ih, b_hh,
                                              fc_w, fc_b, out);
}